// round 4
// baseline (speedup 1.0000x reference)
#include <cuda_runtime.h>
#include <cuda_bf16.h>
#include <math.h>

#define D  128
#define BB 512
#define NN 512
#define BN (BB*NN)
#define APAD 136   // padded bf16 row (272B; 272 mod 128 = 16 -> LDSM conflict-free)
#define MROW 64    // gemm rows per block

// ---- scratch (static device arrays) ----
__device__ __align__(16) __nv_bfloat16 g_W1h[D*D];   // bf16 hi of (Wk@Wa1)^T [d][k]
__device__ __align__(16) __nv_bfloat16 g_W1l[D*D];   // bf16 lo residual
__device__ float g_crel[BB*D];                       // rel @ Wa3 + b_att
__device__ float g_fkW[BN*D];                        // key @ W1 (active rows)
__device__ int   g_idx[BN];                          // compacted active rows
__device__ int   g_count;

__device__ __forceinline__ float lrelu(float x) { return x > 0.f ? x : 0.01f*x; }

// ---- block reductions for blockDim == 512 ----
__device__ __forceinline__ float block_sum512(float v, float* scratch) {
    int lane = threadIdx.x & 31, w = threadIdx.x >> 5;
    #pragma unroll
    for (int o = 16; o > 0; o >>= 1) v += __shfl_down_sync(0xffffffffu, v, o);
    if (lane == 0) scratch[w] = v;
    __syncthreads();
    if (threadIdx.x < 16) {
        v = scratch[threadIdx.x];
        #pragma unroll
        for (int o = 8; o > 0; o >>= 1) v += __shfl_down_sync(0xffffu, v, o, 16);
        if (threadIdx.x == 0) scratch[0] = v;
    }
    __syncthreads();
    float r = scratch[0];
    __syncthreads();
    return r;
}

__device__ __forceinline__ float block_max512(float v, float* scratch) {
    int lane = threadIdx.x & 31, w = threadIdx.x >> 5;
    #pragma unroll
    for (int o = 16; o > 0; o >>= 1) v = fmaxf(v, __shfl_down_sync(0xffffffffu, v, o));
    if (lane == 0) scratch[w] = v;
    __syncthreads();
    if (threadIdx.x < 16) {
        v = scratch[threadIdx.x];
        #pragma unroll
        for (int o = 8; o > 0; o >>= 1) v = fmaxf(v, __shfl_down_sync(0xffffu, v, o, 16));
        if (threadIdx.x == 0) scratch[0] = v;
    }
    __syncthreads();
    float r = scratch[0];
    __syncthreads();
    return r;
}

// ---- prep: W1 (split bf16, transposed) ; crel ; zero g_count ----
__global__ void __launch_bounds__(128) prep_kernel(
    const float* __restrict__ Wk, const float* __restrict__ W_att,
    const float* __restrict__ b_att, const float* __restrict__ rel)
{
    int blk = blockIdx.x;
    int t = threadIdx.x;
    if (blk == 0 && t == 0) g_count = 0;
    __shared__ float row_s[D];
    if (blk < D) {
        int k = blk;
        row_s[t] = Wk[k*D + t];
        __syncthreads();
        float acc = 0.f;
        #pragma unroll 8
        for (int j = 0; j < D; j++) acc += row_s[j] * W_att[j*D + t];
        __nv_bfloat16 hi = __float2bfloat16_rn(acc);
        __nv_bfloat16 lo = __float2bfloat16_rn(acc - __bfloat162float(hi));
        g_W1h[t*D + k] = hi;
        g_W1l[t*D + k] = lo;
    } else {
        int b = blk - D;
        row_s[t] = rel[b*D + t];
        __syncthreads();
        float acc = b_att[t];
        #pragma unroll 8
        for (int j = 0; j < D; j++) acc += row_s[j] * W_att[(2*D + j)*D + t];
        g_crel[b*D + t] = acc;
    }
}

// ---- warp-aggregated compaction of active rows ----
__global__ void __launch_bounds__(256) compact_kernel(const int* __restrict__ mask) {
    int r = blockIdx.x * 256 + threadIdx.x;
    bool act = (mask[r] != 0);
    unsigned bal = __ballot_sync(0xffffffffu, act);
    int lane = threadIdx.x & 31;
    int tot = __popc(bal);
    int base = 0;
    if (lane == 0 && tot) base = atomicAdd(&g_count, tot);
    base = __shfl_sync(0xffffffffu, base, 0);
    if (act) g_idx[base + __popc(bal & ((1u << lane) - 1u))] = r;
}

// ---- tensor-core GEMM: M=64 tile (2 blocks/SM), bf16 3-product split ----
__device__ __forceinline__ void mma_bf16(float (&d)[4], const unsigned (&a)[4],
                                         const unsigned (&b)[2]) {
    asm volatile(
        "mma.sync.aligned.m16n8k16.row.col.f32.bf16.bf16.f32 "
        "{%0,%1,%2,%3}, {%4,%5,%6,%7}, {%8,%9}, {%0,%1,%2,%3};"
        : "+f"(d[0]), "+f"(d[1]), "+f"(d[2]), "+f"(d[3])
        : "r"(a[0]), "r"(a[1]), "r"(a[2]), "r"(a[3]), "r"(b[0]), "r"(b[1]));
}

#define LDSM_X4(r0,r1,r2,r3,addr) \
    asm volatile("ldmatrix.sync.aligned.m8n8.x4.shared.b16 {%0,%1,%2,%3}, [%4];" \
                 : "=r"(r0), "=r"(r1), "=r"(r2), "=r"(r3) : "r"(addr))

__global__ void __launch_bounds__(256) gemm_kernel(const float* __restrict__ key) {
    extern __shared__ char sh[];
    __nv_bfloat16* Ah = (__nv_bfloat16*)sh;            // [64][APAD]
    __nv_bfloat16* Al = Ah + MROW*APAD;
    __nv_bfloat16* Bh = Al + MROW*APAD;                // [128][APAD]
    __nv_bfloat16* Bl = Bh + D*APAD;
    __shared__ int ridx[MROW];

    int cnt = g_count;
    int base = blockIdx.x * MROW;
    if (base >= cnt) return;
    int tid = threadIdx.x;

    if (tid < MROW) ridx[tid] = (base + tid < cnt) ? g_idx[base + tid] : -1;
    __syncthreads();

    // B copy with uint4 (8 bf16 per op). row d: 16 uint4 src, dst stride 17 uint4.
    {
        uint4* dBh = (uint4*)Bh;
        uint4* dBl = (uint4*)Bl;
        const uint4* sBh = (const uint4*)g_W1h;
        const uint4* sBl = (const uint4*)g_W1l;
        for (int i = tid; i < D*16; i += 256) {
            int d = i >> 4, c = i & 15;
            dBh[d*17 + c] = sBh[i];
            dBl[d*17 + c] = sBl[i];
        }
    }
    // A: 4 threads per row, 32 floats each, split into hi/lo bf16
    {
        int r = tid >> 2, part = tid & 3;
        int gr = ridx[r];
        const float* src = (gr >= 0) ? key + (size_t)gr * D + part*32 : (const float*)0;
        #pragma unroll
        for (int c = 0; c < 32; c += 4) {
            float4 v = src ? *(const float4*)(src + c)
                           : make_float4(0.f, 0.f, 0.f, 0.f);
            int col = part*32 + c;
            __nv_bfloat16 h0 = __float2bfloat16_rn(v.x);
            __nv_bfloat16 h1 = __float2bfloat16_rn(v.y);
            __nv_bfloat16 h2 = __float2bfloat16_rn(v.z);
            __nv_bfloat16 h3 = __float2bfloat16_rn(v.w);
            __nv_bfloat16 l0 = __float2bfloat16_rn(v.x - __bfloat162float(h0));
            __nv_bfloat16 l1 = __float2bfloat16_rn(v.y - __bfloat162float(h1));
            __nv_bfloat16 l2 = __float2bfloat16_rn(v.z - __bfloat162float(h2));
            __nv_bfloat16 l3 = __float2bfloat16_rn(v.w - __bfloat162float(h3));
            __nv_bfloat162* ph = (__nv_bfloat162*)(Ah + r*APAD + col);
            __nv_bfloat162* pl = (__nv_bfloat162*)(Al + r*APAD + col);
            ph[0] = __nv_bfloat162(h0, h1); ph[1] = __nv_bfloat162(h2, h3);
            pl[0] = __nv_bfloat162(l0, l1); pl[1] = __nv_bfloat162(l2, l3);
        }
    }
    __syncthreads();

    int w = tid >> 5, lane = tid & 31;
    int wr = w >> 1;        // warp rows [wr*16, +16)
    int wc = w & 1;         // warp cols [wc*64, +64)
    int grp = lane >> 2, q = lane & 3;

    int a_row = lane & 15;
    int a_koff = (lane >> 4) * 8;
    int b_row = (lane & 7) + ((lane >> 4) << 3);
    int b_koff = ((lane >> 3) & 1) * 8;

    unsigned uAh = (unsigned)__cvta_generic_to_shared(Ah);
    unsigned uAl = (unsigned)__cvta_generic_to_shared(Al);
    unsigned uBh = (unsigned)__cvta_generic_to_shared(Bh);
    unsigned uBl = (unsigned)__cvta_generic_to_shared(Bl);

    float acc[8][4];
    #pragma unroll
    for (int nt = 0; nt < 8; nt++)
        #pragma unroll
        for (int i = 0; i < 4; i++) acc[nt][i] = 0.f;

    #pragma unroll
    for (int ks = 0; ks < 8; ks++) {
        int k0 = ks * 16;
        unsigned ah[4], al[4];
        {
            unsigned off = (unsigned)(((wr*16 + a_row)*APAD + k0 + a_koff) * 2);
            LDSM_X4(ah[0], ah[1], ah[2], ah[3], uAh + off);
            LDSM_X4(al[0], al[1], al[2], al[3], uAl + off);
        }
        unsigned bh[8][2], bl[8][2];
        #pragma unroll
        for (int p = 0; p < 4; p++) {
            unsigned off = (unsigned)(((wc*64 + p*16 + b_row)*APAD + k0 + b_koff) * 2);
            LDSM_X4(bh[2*p][0], bh[2*p][1], bh[2*p+1][0], bh[2*p+1][1], uBh + off);
            LDSM_X4(bl[2*p][0], bl[2*p][1], bl[2*p+1][0], bl[2*p+1][1], uBl + off);
        }
        #pragma unroll
        for (int nt = 0; nt < 8; nt++) {
            mma_bf16(acc[nt], ah, bh[nt]);
            mma_bf16(acc[nt], ah, bl[nt]);
            mma_bf16(acc[nt], al, bh[nt]);
        }
    }

    int row = wr*16 + grp;
    int g1 = ridx[row], g2 = ridx[row + 8];
    #pragma unroll
    for (int nt = 0; nt < 8; nt++) {
        int col = wc*64 + nt*8 + q*2;
        if (g1 >= 0)
            *(float2*)(g_fkW + (size_t)g1 * D + col) =
                make_float2(acc[nt][0], acc[nt][1]);
        if (g2 >= 0)
            *(float2*)(g_fkW + (size_t)g2 * D + col) =
                make_float2(acc[nt][2], acc[nt][3]);
    }
}

// ---- fused 3-hop kernel: one block per b, hops loop in-block ----
__global__ void __launch_bounds__(512) hop3_kernel(
    const float* __restrict__ e1,
    const float* __restrict__ value,
    const int*   __restrict__ mask,
    const float* __restrict__ W_att,
    const float* __restrict__ W_lin,
    const float* __restrict__ b_lin,
    const float* __restrict__ Wv,
    float* __restrict__ out)
{
    __shared__ __align__(16) float u_s[D];
    __shared__ __align__(16) float c_s[D];
    __shared__ float ub_s[D];
    __shared__ float crel_s[D];
    __shared__ float att_s[NN];
    __shared__ unsigned short act_s[NN];
    __shared__ int wcnt[16];
    __shared__ int wbase[17];
    __shared__ float red_s[16*D];
    __shared__ float scratch[16];

    int b = blockIdx.x;
    int tid = threadIdx.x;
    int lane = tid & 31, w = tid >> 5;

    if (tid < D) u_s[tid] = e1[b*D + tid];
    if (tid >= 256 && tid < 256 + D) crel_s[tid - 256] = g_crel[b*D + tid - 256];

    // per-b compaction of active n (done once)
    {
        bool act = (mask[b*NN + tid] != 0);
        unsigned bal = __ballot_sync(0xffffffffu, act);
        if (lane == 0) wcnt[w] = __popc(bal);
        __syncthreads();
        if (tid == 0) {
            int s = 0;
            #pragma unroll
            for (int i = 0; i < 16; i++) { wbase[i] = s; s += wcnt[i]; }
            wbase[16] = s;
        }
        __syncthreads();
        if (act) {
            int pos = wbase[w] + __popc(bal & ((1u << lane) - 1u));
            act_s[pos] = (unsigned short)tid;
        }
    }
    int acnt = wbase[16];
    const float* fk_b = g_fkW + (size_t)b * NN * D;
    const float* v_b  = value + (size_t)b * NN * D;
    __syncthreads();

    for (int h = 0; h < 3; h++) {
        // c = u@Wa2 + crel (tid<128) ; ub = lrelu(u@W_lin + b_lin) (128..255)
        if (tid < D) {
            int d = tid;
            float c = crel_s[d];
            #pragma unroll 8
            for (int k = 0; k < D; k++) c += u_s[k] * W_att[(D + k)*D + d];
            c_s[d] = c;
        } else if (tid < 2*D) {
            int d = tid - D;
            float v = b_lin[d];
            #pragma unroll 8
            for (int k = 0; k < D; k++) v += u_s[k] * W_lin[k*D + d];
            ub_s[d] = lrelu(v);
        }
        __syncthreads();

        // masked-row logit (exact: fk rows are 0 there)
        float att0 = block_sum512(tid < D ? lrelu(c_s[tid]) : 0.f, scratch);

        // pass 1: logits for active rows (warp per row, 4-way)
        float4 cv = *(const float4*)&c_s[lane*4];
        for (int j0 = 0; j0 < acnt; j0 += 64) {
            float ss[4];
            int   ii_n[4];
            bool  vv[4];
            #pragma unroll
            for (int i = 0; i < 4; i++) {
                int idx = j0 + i*16 + w;
                vv[i] = (idx < acnt);
                ii_n[i] = vv[i] ? (int)act_s[idx] : 0;
                ss[i] = 0.f;
            }
            #pragma unroll
            for (int i = 0; i < 4; i++) if (vv[i]) {
                float4 v = *(const float4*)(fk_b + (size_t)ii_n[i]*D + lane*4);
                ss[i] = lrelu(v.x+cv.x) + lrelu(v.y+cv.y) + lrelu(v.z+cv.z) + lrelu(v.w+cv.w);
            }
            #pragma unroll
            for (int o = 16; o > 0; o >>= 1)
                #pragma unroll
                for (int i = 0; i < 4; i++)
                    ss[i] += __shfl_down_sync(0xffffffffu, ss[i], o);
            if (lane == 0) {
                #pragma unroll
                for (int i = 0; i < 4; i++) {
                    int idx = j0 + i*16 + w;
                    if (idx < acnt) att_s[idx] = ss[i];
                }
            }
        }
        __syncthreads();

        // softmax over active logits; max includes masked logits (= att0)
        float mx = att0;
        for (int i = tid; i < acnt; i += 512) mx = fmaxf(mx, att_s[i]);
        mx = block_max512(mx, scratch);

        float Sp = 0.f;
        for (int i = tid; i < acnt; i += 512) {
            float e = expf(att_s[i] - mx);
            att_s[i] = e;
            Sp += e;
        }
        float S = block_sum512(Sp, scratch) + 1e-5f;

        // pass 2: q[d] = sum over active rows of e * value[b,n,d]
        float o0 = 0.f, o1 = 0.f, o2 = 0.f, o3 = 0.f;
        for (int j0 = 0; j0 < acnt; j0 += 64) {
            #pragma unroll
            for (int i = 0; i < 4; i++) {
                int idx = j0 + i*16 + w;
                if (idx < acnt) {
                    int n = (int)act_s[idx];
                    float e = att_s[idx];
                    float4 v = *(const float4*)(v_b + (size_t)n*D + lane*4);
                    o0 += e*v.x; o1 += e*v.y; o2 += e*v.z; o3 += e*v.w;
                }
            }
        }
        red_s[w*D + lane*4 + 0] = o0;
        red_s[w*D + lane*4 + 1] = o1;
        red_s[w*D + lane*4 + 2] = o2;
        red_s[w*D + lane*4 + 3] = o3;
        __syncthreads();

        if (tid < D) {
            float o = 0.f;
            #pragma unroll
            for (int ww = 0; ww < 16; ww++) o += red_s[ww*D + tid];
            c_s[tid] = o / S;          // q = p @ value
        }
        __syncthreads();

        if (tid < D) {
            float ov = 0.f;
            #pragma unroll 8
            for (int k = 0; k < D; k++) ov += c_s[k] * Wv[k*D + tid];
            u_s[tid] = ub_s[tid] + ov;  // pre-norm x
        }
        __syncthreads();

        float nrm2 = block_sum512(tid < D ? u_s[tid]*u_s[tid] : 0.f, scratch);
        float norm = sqrtf(nrm2);
        if (tid < D) {
            float x = u_s[tid];
            float un = (norm > 1e-12f) ? (x / norm) : (x * 1e12f);
            u_s[tid] = un;
            if (h == 2) out[b*D + tid] = un;
        }
        __syncthreads();
    }
}

extern "C" void kernel_launch(void* const* d_in, const int* in_sizes, int n_in,
                              void* d_out, int out_size) {
    const float* e1    = (const float*)d_in[0];
    const float* rel   = (const float*)d_in[1];
    const float* key   = (const float*)d_in[2];
    const float* value = (const float*)d_in[3];
    const int*   mask  = (const int*)  d_in[4];
    const float* Wk    = (const float*)d_in[5];
    const float* Wv    = (const float*)d_in[6];
    const float* Wlin  = (const float*)d_in[7];
    const float* blin  = (const float*)d_in[8];
    const float* Watt  = (const float*)d_in[9];
    const float* batt  = (const float*)d_in[10];
    float* out = (float*)d_out;

    prep_kernel<<<D + BB, 128>>>(Wk, Watt, batt, rel);
    compact_kernel<<<BN/256, 256>>>(mask);

    int gemm_smem = (2*MROW + 2*D) * APAD * (int)sizeof(__nv_bfloat16);
    cudaFuncSetAttribute(gemm_kernel, cudaFuncAttributeMaxDynamicSharedMemorySize,
                         gemm_smem);
    gemm_kernel<<<BN/MROW, 256, gemm_smem>>>(key);

    hop3_kernel<<<BB, 512>>>(e1, value, mask, Watt, Wlin, blin, Wv, out);
}